// round 13
// baseline (speedup 1.0000x reference)
#include <cuda_runtime.h>
#include <cstdint>

// Shape (fixed): u[B=16, T=1024, H=2048] f32, alpha[H], beta[H], seed int32
#define BB 16
#define TT 1024
#define HH 2048
#define HC 8            // channels per CTA (= warps per CTA)
#define NTHR 256
#define FULLM 0xFFFFFFFFu

#define TILE_FLOATS (TT * HC)    // 8192 floats = 32 KB

// XOR-swizzled tile layout (see R4): conflict-free column gathers.
__device__ __forceinline__ int swz(int t, int c) {
    int L = t >> 5;
    return (L << 8) + ((((t & 31) << 3) + c) ^ L);
}

__device__ __forceinline__ unsigned rotl32(unsigned x, int r) {
    return __funnelshift_l(x, x, r);
}

// XLA f32 tanh (Eigen generic_fast_tanh_float), plain mul/add (no contraction).
__device__ __forceinline__ float tanh_xla(float x) {
    float ax = fabsf(x);
    float xc = fminf(fmaxf(x, -7.90531110763549805f), 7.90531110763549805f);
    float x2 = __fmul_rn(xc, xc);
    float np = __fadd_rn(__fmul_rn(x2, -2.76076847742355e-16f), 2.00018790482477e-13f);
    np = __fadd_rn(__fmul_rn(x2, np), -8.60467152213735e-11f);
    np = __fadd_rn(__fmul_rn(x2, np),  5.12229709037114e-08f);
    np = __fadd_rn(__fmul_rn(x2, np),  1.48572235717979e-05f);
    np = __fadd_rn(__fmul_rn(x2, np),  6.37261928875436e-04f);
    np = __fadd_rn(__fmul_rn(x2, np),  4.89352455891786e-03f);
    float num = __fmul_rn(xc, np);
    float dp = __fadd_rn(__fmul_rn(x2, 1.19825839466702e-06f), 1.18534705686654e-04f);
    dp = __fadd_rn(__fmul_rn(x2, dp), 2.26843463243900e-03f);
    dp = __fadd_rn(__fmul_rn(x2, dp), 4.89352518554385e-03f);
    float t = __fdiv_rn(num, dp);
    return (ax < 0.0004f) ? x : t;
}

// Exact jax.lax.associative_scan tree over 1024 elems/channel:
// in-place register Blelloch (levels 0-4) + warp-shuffle Blelloch (5-9).
__device__ __forceinline__ void tree_scan(float (&v)[32], const float* A, int lane) {
    #pragma unroll
    for (int s = 0; s < 5; s++) {
        const int h = 1 << s, st = h << 1;
        #pragma unroll
        for (int p = st - 1; p < 32; p += st)
            v[p] = __fadd_rn(__fmul_rn(A[s], v[p - h]), v[p]);
    }
    float w = v[31];
    #pragma unroll
    for (int m = 0; m < 5; m++) {
        float t = __shfl_up_sync(FULLM, w, 1 << m);
        if ((lane & ((2 << m) - 1)) == ((2 << m) - 1))
            w = __fadd_rn(__fmul_rn(A[5 + m], t), w);
    }
    #pragma unroll
    for (int m = 3; m >= 0; m--) {
        float t = __shfl_up_sync(FULLM, w, 1 << m);
        if (((lane & ((2 << m) - 1)) == ((1 << m) - 1)) && (lane >= (2 << m)))
            w = __fadd_rn(__fmul_rn(A[5 + m], t), w);
    }
    float P = __shfl_up_sync(FULLM, w, 1);
    if (lane == 0) P = 0.0f;
    v[31] = w;
    #pragma unroll
    for (int s = 4; s >= 0; s--) {
        const int h = 1 << s, st = h << 1;
        #pragma unroll
        for (int p = h - 1; p < 32; p += st) {
            float left = (p < st) ? P : v[p - h];
            v[p] = __fadd_rn(__fmul_rn(A[s], left), v[p]);
        }
    }
}

// Full bit-exact spike decision for one gated element f = t*8 + c.
__device__ __forceinline__ void spike_eval(const float* S, int f,
                                           unsigned Cbase, unsigned ks1, unsigned ks2v,
                                           unsigned& gi, bool& spk) {
    int t = f >> 3, c = f & 7;
    float V = S[swz(t, c)];
    float U = __fadd_rn(V, -1.0f);                       // V - THRESHOLD
    float cv  = cosf(__fmul_rn(6.2831855f, U));          // cos(f32(2pi)*U)
    float th  = tanh_xla(__fmul_rn(50.0f, U));           // logistic(100U)
    float sig = __fadd_rn(__fmul_rn(0.5f, th), 0.5f);
    float p   = fmaxf(__fmul_rn(cv, sig), 0.0f);

    gi = Cbase + (unsigned)t * (unsigned)HH + (unsigned)c;

    // threefry2x32(key=(0,seed), counts=(0, gi)); fold out0^out1
    unsigned x0 = 0u;
    unsigned x1 = gi + ks1;
    #define TFR(r_) { x0 += x1; x1 = rotl32(x1, (r_)); x1 ^= x0; }
    TFR(13) TFR(15) TFR(26) TFR(6)   x0 += ks1;  x1 += ks2v + 1u;
    TFR(17) TFR(29) TFR(16) TFR(24)  x0 += ks2v; x1 += 2u;
    TFR(13) TFR(15) TFR(26) TFR(6)                x1 += ks1 + 3u;
    TFR(17) TFR(29) TFR(16) TFR(24)  x0 += ks1;  x1 += ks2v + 4u;
    TFR(13) TFR(15) TFR(26) TFR(6)   x0 += ks2v; x1 += 5u;
    #undef TFR
    unsigned bits = x0 ^ x1;
    float uf = __fadd_rn(__uint_as_float((bits >> 9) | 0x3F800000u), -1.0f);
    spk = (uf < p);
}

__global__ void __launch_bounds__(NTHR, 4)   // pin <=64 regs (occupancy knee)
cubalif_kernel(const float* __restrict__ u,
               const float* __restrict__ alpha,
               const float* __restrict__ beta,
               const int*   __restrict__ seedp,
               float* __restrict__ out) {
    __shared__ float S[TILE_FLOATS];                 // 32 KB (V values)
    __shared__ unsigned short Lst[TILE_FLOATS];      // 16 KB CTA-wide index list
    __shared__ int Wsum[HC];                         // per-warp gate counts

    const int tid  = threadIdx.x;
    const int lane = tid & 31;
    const int wrp  = tid >> 5;            // warp id in CTA = channel (scan & gate)
    const int b    = blockIdx.x >> 8;
    const int h0   = (blockIdx.x & 255) * HC;

    // ---- stage u tile [T][8] into swizzled smem + zero-fill out tile ----
    const float4* up4 = reinterpret_cast<const float4*>(u + ((size_t)b * TT) * HH + h0);
    float* outp = out + ((size_t)b * TT) * HH + h0;
    const float4 z4 = make_float4(0.f, 0.f, 0.f, 0.f);
    #pragma unroll
    for (int k = 0; k < TILE_FLOATS / 4 / NTHR; k++) {   // 8 iters
        int i4 = k * NTHR + tid;
        int t = i4 >> 1, q = i4 & 1;
        float4 d = up4[(size_t)t * (HH / 4) + q];
        int c0 = q * 4;
        S[swz(t, c0 + 0)] = d.x;
        S[swz(t, c0 + 1)] = d.y;
        S[swz(t, c0 + 2)] = d.z;
        S[swz(t, c0 + 3)] = d.w;
        *reinterpret_cast<float4*>(outp + (size_t)t * HH + c0) = z4;
    }
    __syncthreads();

    // ---- gather 32 time steps of channel wrp (conflict-free) ----
    float v[32];
    #pragma unroll
    for (int j = 0; j < 32; j++)
        v[j] = S[(lane << 8) + (((j << 3) + wrp) ^ lane)];

    // ---- decay powers + two scans (bit-exact vs JAX) ----
    float A[10];
    A[0] = fminf(fmaxf(alpha[h0 + wrp], 0.0f), 1.0f);
    #pragma unroll
    for (int s = 1; s < 10; s++) A[s] = __fmul_rn(A[s - 1], A[s - 1]);
    tree_scan(v, A, lane);                // synaptic current

    A[0] = fminf(fmaxf(beta[h0 + wrp], 0.0f), 1.0f);
    #pragma unroll
    for (int s = 1; s < 10; s++) A[s] = __fmul_rn(A[s - 1], A[s - 1]);
    tree_scan(v, A, lane);                // membrane potential V

    // ===== Phase A (register-resident): gate mask + CTA-wide prefix =====
    // p > 0  <=>  cosf(2pi*U) > 0  (Eigen-sigmoid strictly positive).
    // cos>0 <=> |U - round(U)| < 0.25 up to rounding; margin fma(|U|,4e-7,.252)
    // over-covers all rounding paths. Over-inclusion safe (Phase B exact).
    unsigned gm = 0u;                     // lane-private gate mask over j=0..31
    #pragma unroll
    for (int j = 0; j < 32; j++) {
        float U = __fadd_rn(v[j], -1.0f);
        float w = __fadd_rn(U, -rintf(U));           // exact (Sterbenz)
        if (fabsf(w) < __fmaf_rn(fabsf(U), 4e-7f, 0.252f)) gm |= (1u << j);
    }
    int cnt  = __popc(gm);
    int incl = cnt;
    #pragma unroll
    for (int s = 1; s < 32; s <<= 1) {
        int tsh = __shfl_up_sync(FULLM, incl, s);
        if (lane >= s) incl += tsh;
    }
    if (lane == 31) Wsum[wrp] = incl;     // warp total
    __syncthreads();

    int wbase = 0, totalC = 0;
    #pragma unroll
    for (int w = 0; w < HC; w++) {
        int s = Wsum[w];
        if (w < wrp) wbase += s;
        totalC += s;
    }
    int myoff = wbase + (incl - cnt);     // CTA-wide exclusive prefix

    // ---- writeback V + fused emission into the CTA-wide list ----
    #pragma unroll
    for (int j = 0; j < 32; j++) {
        S[(lane << 8) + (((j << 3) + wrp) ^ lane)] = v[j];
        if (gm & (1u << j)) {
            Lst[myoff] = (unsigned short)((((lane << 5) + j) << 3) | wrp); // t*8+c
            myoff++;
        }
    }
    __syncthreads();   // V + Lst visible CTA-wide

    // ===== Phase B: CTA-cooperative, 2-wide ILP, perfectly balanced =====
    const unsigned k2   = (unsigned)seedp[0];    // key=(0,seed): ks0=0
    const unsigned ks1  = k2;
    const unsigned ks2v = k2 ^ 0x1BD11BDAu;
    const unsigned Cbase = (unsigned)(b * TT) * (unsigned)HH + (unsigned)h0;

    for (int s0 = 0; s0 < totalC; s0 += 2 * NTHR) {
        int r0 = s0 + tid;
        int r1 = s0 + NTHR + tid;
        bool a0 = r0 < totalC, a1 = r1 < totalC;
        int f0 = (int)Lst[a0 ? r0 : 0];
        int f1 = (int)Lst[a1 ? r1 : 0];
        unsigned gi0, gi1; bool s0k, s1k;
        spike_eval(S, f0, Cbase, ks1, ks2v, gi0, s0k);
        spike_eval(S, f1, Cbase, ks1, ks2v, gi1, s1k);
        if (a0 && s0k) out[gi0] = 1.0f;   // overwrite the zero
        if (a1 && s1k) out[gi1] = 1.0f;   // (dup ranks write same value: benign)
    }
}

extern "C" void kernel_launch(void* const* d_in, const int* in_sizes, int n_in,
                              void* d_out, int out_size) {
    const float* u     = (const float*)d_in[0];
    const float* alpha = (const float*)d_in[1];
    const float* beta  = (const float*)d_in[2];
    const int*   seed  = (const int*)d_in[3];
    float* out = (float*)d_out;
    (void)in_sizes; (void)n_in; (void)out_size;

    dim3 grid(BB * (HH / HC));   // 4096 CTAs
    cubalif_kernel<<<grid, NTHR>>>(u, alpha, beta, seed, out);
}

// round 14
// speedup vs baseline: 1.1877x; 1.1877x over previous
#include <cuda_runtime.h>
#include <cstdint>

// Shape (fixed): u[B=16, T=1024, H=2048] f32, alpha[H], beta[H], seed int32
#define BB 16
#define TT 1024
#define HH 2048
#define HC 8            // channels per CTA (= warps per CTA)
#define NTHR 256
#define FULLM 0xFFFFFFFFu

#define TILE_FLOATS (TT * HC)    // 8192 floats = 32 KB

// XOR-swizzled tile layout (see R4): conflict-free column gathers.
__device__ __forceinline__ int swz(int t, int c) {
    int L = t >> 5;
    return (L << 8) + ((((t & 31) << 3) + c) ^ L);
}

__device__ __forceinline__ unsigned rotl32(unsigned x, int r) {
    return __funnelshift_l(x, x, r);
}

// XLA f32 tanh (Eigen generic_fast_tanh_float), plain mul/add (no contraction).
__device__ __forceinline__ float tanh_xla(float x) {
    float ax = fabsf(x);
    float xc = fminf(fmaxf(x, -7.90531110763549805f), 7.90531110763549805f);
    float x2 = __fmul_rn(xc, xc);
    float np = __fadd_rn(__fmul_rn(x2, -2.76076847742355e-16f), 2.00018790482477e-13f);
    np = __fadd_rn(__fmul_rn(x2, np), -8.60467152213735e-11f);
    np = __fadd_rn(__fmul_rn(x2, np),  5.12229709037114e-08f);
    np = __fadd_rn(__fmul_rn(x2, np),  1.48572235717979e-05f);
    np = __fadd_rn(__fmul_rn(x2, np),  6.37261928875436e-04f);
    np = __fadd_rn(__fmul_rn(x2, np),  4.89352455891786e-03f);
    float num = __fmul_rn(xc, np);
    float dp = __fadd_rn(__fmul_rn(x2, 1.19825839466702e-06f), 1.18534705686654e-04f);
    dp = __fadd_rn(__fmul_rn(x2, dp), 2.26843463243900e-03f);
    dp = __fadd_rn(__fmul_rn(x2, dp), 4.89352518554385e-03f);
    float t = __fdiv_rn(num, dp);
    return (ax < 0.0004f) ? x : t;
}

// Exact jax.lax.associative_scan tree over 1024 elems/channel:
// in-place register Blelloch (levels 0-4) + warp-shuffle Blelloch (5-9).
__device__ __forceinline__ void tree_scan(float (&v)[32], const float* A, int lane) {
    #pragma unroll
    for (int s = 0; s < 5; s++) {
        const int h = 1 << s, st = h << 1;
        #pragma unroll
        for (int p = st - 1; p < 32; p += st)
            v[p] = __fadd_rn(__fmul_rn(A[s], v[p - h]), v[p]);
    }
    float w = v[31];
    #pragma unroll
    for (int m = 0; m < 5; m++) {
        float t = __shfl_up_sync(FULLM, w, 1 << m);
        if ((lane & ((2 << m) - 1)) == ((2 << m) - 1))
            w = __fadd_rn(__fmul_rn(A[5 + m], t), w);
    }
    #pragma unroll
    for (int m = 3; m >= 0; m--) {
        float t = __shfl_up_sync(FULLM, w, 1 << m);
        if (((lane & ((2 << m) - 1)) == ((1 << m) - 1)) && (lane >= (2 << m)))
            w = __fadd_rn(__fmul_rn(A[5 + m], t), w);
    }
    float P = __shfl_up_sync(FULLM, w, 1);
    if (lane == 0) P = 0.0f;
    v[31] = w;
    #pragma unroll
    for (int s = 4; s >= 0; s--) {
        const int h = 1 << s, st = h << 1;
        #pragma unroll
        for (int p = h - 1; p < 32; p += st) {
            float left = (p < st) ? P : v[p - h];
            v[p] = __fadd_rn(__fmul_rn(A[s], left), v[p]);
        }
    }
}

// Full bit-exact spike decision from V (no smem lookup).
__device__ __forceinline__ bool spike_eval(float V, unsigned gi,
                                           unsigned ks1, unsigned ks2v) {
    float U = __fadd_rn(V, -1.0f);                       // V - THRESHOLD
    float cv  = cosf(__fmul_rn(6.2831855f, U));          // cos(f32(2pi)*U)
    float th  = tanh_xla(__fmul_rn(50.0f, U));           // logistic(100U)
    float sig = __fadd_rn(__fmul_rn(0.5f, th), 0.5f);
    float p   = fmaxf(__fmul_rn(cv, sig), 0.0f);

    // threefry2x32(key=(0,seed), counts=(0, gi)); fold out0^out1
    unsigned x0 = 0u;
    unsigned x1 = gi + ks1;
    #define TFR(r_) { x0 += x1; x1 = rotl32(x1, (r_)); x1 ^= x0; }
    TFR(13) TFR(15) TFR(26) TFR(6)   x0 += ks1;  x1 += ks2v + 1u;
    TFR(17) TFR(29) TFR(16) TFR(24)  x0 += ks2v; x1 += 2u;
    TFR(13) TFR(15) TFR(26) TFR(6)                x1 += ks1 + 3u;
    TFR(17) TFR(29) TFR(16) TFR(24)  x0 += ks1;  x1 += ks2v + 4u;
    TFR(13) TFR(15) TFR(26) TFR(6)   x0 += ks2v; x1 += 5u;
    #undef TFR
    unsigned bits = x0 ^ x1;
    float uf = __fadd_rn(__uint_as_float((bits >> 9) | 0x3F800000u), -1.0f);
    return (uf < p);
}

__global__ void __launch_bounds__(NTHR, 4)   // pin <=64 regs (occupancy knee)
cubalif_kernel(const float* __restrict__ u,
               const float* __restrict__ alpha,
               const float* __restrict__ beta,
               const int*   __restrict__ seedp,
               float* __restrict__ out) {
    // SB: staging tile during load/gather, then REUSED as gated-V value list.
    __shared__ float SB[TILE_FLOATS];                // 32 KB
    __shared__ unsigned short Lst[TILE_FLOATS];      // 16 KB gated t-indices

    const int tid  = threadIdx.x;
    const int lane = tid & 31;
    const int wrp  = tid >> 5;            // warp id in CTA = channel
    const int b    = blockIdx.x >> 8;
    const int h0   = (blockIdx.x & 255) * HC;

    // ---- stage u tile [T][8] into swizzled smem + zero-fill out tile ----
    const float4* up4 = reinterpret_cast<const float4*>(u + ((size_t)b * TT) * HH + h0);
    float* outp = out + ((size_t)b * TT) * HH + h0;
    const float4 z4 = make_float4(0.f, 0.f, 0.f, 0.f);
    #pragma unroll
    for (int k = 0; k < TILE_FLOATS / 4 / NTHR; k++) {   // 8 iters
        int i4 = k * NTHR + tid;
        int t = i4 >> 1, q = i4 & 1;
        float4 d = up4[(size_t)t * (HH / 4) + q];
        int c0 = q * 4;
        SB[swz(t, c0 + 0)] = d.x;
        SB[swz(t, c0 + 1)] = d.y;
        SB[swz(t, c0 + 2)] = d.z;
        SB[swz(t, c0 + 3)] = d.w;
        *reinterpret_cast<float4*>(outp + (size_t)t * HH + c0) = z4;
    }
    __syncthreads();

    // ---- gather 32 time steps of channel wrp (conflict-free) ----
    float v[32];
    #pragma unroll
    for (int j = 0; j < 32; j++)
        v[j] = SB[(lane << 8) + (((j << 3) + wrp) ^ lane)];
    __syncthreads();   // all tile reads done -> SB reusable as value list

    // ---- decay powers + two scans (bit-exact vs JAX) ----
    float A[10];
    A[0] = fminf(fmaxf(alpha[h0 + wrp], 0.0f), 1.0f);
    #pragma unroll
    for (int s = 1; s < 10; s++) A[s] = __fmul_rn(A[s - 1], A[s - 1]);
    tree_scan(v, A, lane);                // synaptic current

    A[0] = fminf(fmaxf(beta[h0 + wrp], 0.0f), 1.0f);
    #pragma unroll
    for (int s = 1; s < 10; s++) A[s] = __fmul_rn(A[s - 1], A[s - 1]);
    tree_scan(v, A, lane);                // membrane potential V

    // ===== Phase A (register-resident): gate mask + warp prefix =====
    // p > 0  <=>  cosf(2pi*U) > 0  (Eigen-sigmoid strictly positive).
    // cos>0 <=> |U - round(U)| < 0.25 up to rounding; margin fma(|U|,4e-7,.252)
    // over-covers all rounding paths. Over-inclusion safe (Phase B exact).
    unsigned gm = 0u;                     // lane-private gate mask over j=0..31
    #pragma unroll
    for (int j = 0; j < 32; j++) {
        float U = __fadd_rn(v[j], -1.0f);
        float w = __fadd_rn(U, -rintf(U));           // exact (Sterbenz)
        if (fabsf(w) < __fmaf_rn(fabsf(U), 4e-7f, 0.252f)) gm |= (1u << j);
    }
    int cnt  = __popc(gm);
    int incl = cnt;
    #pragma unroll
    for (int s = 1; s < 32; s <<= 1) {
        int tsh = __shfl_up_sync(FULLM, incl, s);
        if (lane >= s) incl += tsh;
    }
    int myoff = incl - cnt;                          // warp-exclusive prefix
    int total = __shfl_sync(FULLM, incl, 31);

    // ---- value-carrying emission: (V, t) pairs; v dies here; no writeback ----
    const int wtile = wrp << 10;
    #pragma unroll
    for (int j = 0; j < 32; j++) {
        if (gm & (1u << j)) {
            SB [wtile + myoff] = v[j];
            Lst[wtile + myoff] = (unsigned short)((lane << 5) + j);   // t
            myoff++;
        }
    }
    __syncwarp();   // own-warp STS -> cross-lane LDS

    // ===== Phase B: per-warp, 2-wide ILP, conflict-free sequential LDS =====
    const unsigned k2   = (unsigned)seedp[0];    // key=(0,seed): ks0=0
    const unsigned ks1  = k2;
    const unsigned ks2v = k2 ^ 0x1BD11BDAu;
    const unsigned CbaseC = (unsigned)(b * TT) * (unsigned)HH + (unsigned)(h0 + wrp);

    for (int s0 = 0; s0 < total; s0 += 64) {
        int r0 = s0 + lane;
        int r1 = s0 + 32 + lane;
        bool a0 = r0 < total, a1 = r1 < total;
        int rr0 = a0 ? r0 : total - 1;
        int rr1 = a1 ? r1 : total - 1;
        float V0 = SB[wtile + rr0];
        float V1 = SB[wtile + rr1];
        int   t0 = (int)Lst[wtile + rr0];
        int   t1 = (int)Lst[wtile + rr1];
        unsigned gi0 = CbaseC + (unsigned)t0 * (unsigned)HH;
        unsigned gi1 = CbaseC + (unsigned)t1 * (unsigned)HH;
        bool s0k = spike_eval(V0, gi0, ks1, ks2v);
        bool s1k = spike_eval(V1, gi1, ks1, ks2v);
        if (a0 && s0k) out[gi0] = 1.0f;   // overwrite the zero
        if (a1 && s1k) out[gi1] = 1.0f;   // (dup ranks write same value: benign)
    }
}

extern "C" void kernel_launch(void* const* d_in, const int* in_sizes, int n_in,
                              void* d_out, int out_size) {
    const float* u     = (const float*)d_in[0];
    const float* alpha = (const float*)d_in[1];
    const float* beta  = (const float*)d_in[2];
    const int*   seed  = (const int*)d_in[3];
    float* out = (float*)d_out;
    (void)in_sizes; (void)n_in; (void)out_size;

    dim3 grid(BB * (HH / HC));   // 4096 CTAs
    cubalif_kernel<<<grid, NTHR>>>(u, alpha, beta, seed, out);
}

// round 15
// speedup vs baseline: 1.1984x; 1.0091x over previous
#include <cuda_runtime.h>
#include <cstdint>

// Shape (fixed): u[B=16, T=1024, H=2048] f32, alpha[H], beta[H], seed int32
#define BB 16
#define TT 1024
#define HH 2048
#define HC 8            // channels per CTA (= warps per CTA)
#define NTHR 256
#define FULLM 0xFFFFFFFFu

#define TILE_FLOATS (TT * HC)    // 8192 floats = 32 KB

// XOR-swizzled tile layout (see R4): conflict-free column gathers.
__device__ __forceinline__ int swz(int t, int c) {
    int L = t >> 5;
    return (L << 8) + ((((t & 31) << 3) + c) ^ L);
}

__device__ __forceinline__ unsigned rotl32(unsigned x, int r) {
    return __funnelshift_l(x, x, r);
}

// XLA f32 tanh (Eigen generic_fast_tanh_float), plain mul/add (no contraction).
__device__ __forceinline__ float tanh_xla(float x) {
    float ax = fabsf(x);
    float xc = fminf(fmaxf(x, -7.90531110763549805f), 7.90531110763549805f);
    float x2 = __fmul_rn(xc, xc);
    float np = __fadd_rn(__fmul_rn(x2, -2.76076847742355e-16f), 2.00018790482477e-13f);
    np = __fadd_rn(__fmul_rn(x2, np), -8.60467152213735e-11f);
    np = __fadd_rn(__fmul_rn(x2, np),  5.12229709037114e-08f);
    np = __fadd_rn(__fmul_rn(x2, np),  1.48572235717979e-05f);
    np = __fadd_rn(__fmul_rn(x2, np),  6.37261928875436e-04f);
    np = __fadd_rn(__fmul_rn(x2, np),  4.89352455891786e-03f);
    float num = __fmul_rn(xc, np);
    float dp = __fadd_rn(__fmul_rn(x2, 1.19825839466702e-06f), 1.18534705686654e-04f);
    dp = __fadd_rn(__fmul_rn(x2, dp), 2.26843463243900e-03f);
    dp = __fadd_rn(__fmul_rn(x2, dp), 4.89352518554385e-03f);
    float t = __fdiv_rn(num, dp);
    return (ax < 0.0004f) ? x : t;
}

// Exact jax.lax.associative_scan tree over 1024 elems/channel:
// in-place register Blelloch (levels 0-4) + warp-shuffle Blelloch (5-9).
__device__ __forceinline__ void tree_scan(float (&v)[32], const float* A, int lane) {
    #pragma unroll
    for (int s = 0; s < 5; s++) {
        const int h = 1 << s, st = h << 1;
        #pragma unroll
        for (int p = st - 1; p < 32; p += st)
            v[p] = __fadd_rn(__fmul_rn(A[s], v[p - h]), v[p]);
    }
    float w = v[31];
    #pragma unroll
    for (int m = 0; m < 5; m++) {
        float t = __shfl_up_sync(FULLM, w, 1 << m);
        if ((lane & ((2 << m) - 1)) == ((2 << m) - 1))
            w = __fadd_rn(__fmul_rn(A[5 + m], t), w);
    }
    #pragma unroll
    for (int m = 3; m >= 0; m--) {
        float t = __shfl_up_sync(FULLM, w, 1 << m);
        if (((lane & ((2 << m) - 1)) == ((1 << m) - 1)) && (lane >= (2 << m)))
            w = __fadd_rn(__fmul_rn(A[5 + m], t), w);
    }
    float P = __shfl_up_sync(FULLM, w, 1);
    if (lane == 0) P = 0.0f;
    v[31] = w;
    #pragma unroll
    for (int s = 4; s >= 0; s--) {
        const int h = 1 << s, st = h << 1;
        #pragma unroll
        for (int p = h - 1; p < 32; p += st) {
            float left = (p < st) ? P : v[p - h];
            v[p] = __fadd_rn(__fmul_rn(A[s], left), v[p]);
        }
    }
}

// Full bit-exact spike decision from V (no smem lookup).
__device__ __forceinline__ bool spike_eval(float V, unsigned gi,
                                           unsigned ks1, unsigned ks2v) {
    float U = __fadd_rn(V, -1.0f);                       // V - THRESHOLD
    float cv  = cosf(__fmul_rn(6.2831855f, U));          // cos(f32(2pi)*U)
    float th  = tanh_xla(__fmul_rn(50.0f, U));           // logistic(100U)
    float sig = __fadd_rn(__fmul_rn(0.5f, th), 0.5f);
    float p   = fmaxf(__fmul_rn(cv, sig), 0.0f);

    // threefry2x32(key=(0,seed), counts=(0, gi)); fold out0^out1
    unsigned x0 = 0u;
    unsigned x1 = gi + ks1;
    #define TFR(r_) { x0 += x1; x1 = rotl32(x1, (r_)); x1 ^= x0; }
    TFR(13) TFR(15) TFR(26) TFR(6)   x0 += ks1;  x1 += ks2v + 1u;
    TFR(17) TFR(29) TFR(16) TFR(24)  x0 += ks2v; x1 += 2u;
    TFR(13) TFR(15) TFR(26) TFR(6)                x1 += ks1 + 3u;
    TFR(17) TFR(29) TFR(16) TFR(24)  x0 += ks1;  x1 += ks2v + 4u;
    TFR(13) TFR(15) TFR(26) TFR(6)   x0 += ks2v; x1 += 5u;
    #undef TFR
    unsigned bits = x0 ^ x1;
    float uf = __fadd_rn(__uint_as_float((bits >> 9) | 0x3F800000u), -1.0f);
    return (uf < p);
}

__global__ void __launch_bounds__(NTHR, 4)   // pin <=64 regs (occupancy knee)
cubalif_kernel(const float* __restrict__ u,
               const float* __restrict__ alpha,
               const float* __restrict__ beta,
               const int*   __restrict__ seedp,
               float* __restrict__ out) {
    // SB: staging tile during load/gather, then REUSED as gated-V value list.
    __shared__ float SB[TILE_FLOATS];                // 32 KB
    __shared__ unsigned short Lst[TILE_FLOATS];      // 16 KB gated t-indices

    const int tid  = threadIdx.x;
    const int lane = tid & 31;
    const int wrp  = tid >> 5;            // warp id in CTA = channel
    const int b    = blockIdx.x >> 8;
    const int h0   = (blockIdx.x & 255) * HC;

    // ---- stage u tile [T][8] into swizzled smem + zero-fill out tile ----
    const float4* up4 = reinterpret_cast<const float4*>(u + ((size_t)b * TT) * HH + h0);
    float* outp = out + ((size_t)b * TT) * HH + h0;
    const float4 z4 = make_float4(0.f, 0.f, 0.f, 0.f);
    #pragma unroll
    for (int k = 0; k < TILE_FLOATS / 4 / NTHR; k++) {   // 8 iters
        int i4 = k * NTHR + tid;
        int t = i4 >> 1, q = i4 & 1;
        float4 d = up4[(size_t)t * (HH / 4) + q];
        int c0 = q * 4;
        SB[swz(t, c0 + 0)] = d.x;
        SB[swz(t, c0 + 1)] = d.y;
        SB[swz(t, c0 + 2)] = d.z;
        SB[swz(t, c0 + 3)] = d.w;
        *reinterpret_cast<float4*>(outp + (size_t)t * HH + c0) = z4;
    }
    __syncthreads();

    // ---- gather 32 time steps of channel wrp (conflict-free) ----
    float v[32];
    #pragma unroll
    for (int j = 0; j < 32; j++)
        v[j] = SB[(lane << 8) + (((j << 3) + wrp) ^ lane)];
    __syncthreads();   // all tile reads done -> SB reusable as value list

    // ---- decay powers + two scans (bit-exact vs JAX) ----
    float A[10];
    A[0] = fminf(fmaxf(alpha[h0 + wrp], 0.0f), 1.0f);
    #pragma unroll
    for (int s = 1; s < 10; s++) A[s] = __fmul_rn(A[s - 1], A[s - 1]);
    tree_scan(v, A, lane);                // synaptic current

    A[0] = fminf(fmaxf(beta[h0 + wrp], 0.0f), 1.0f);
    #pragma unroll
    for (int s = 1; s < 10; s++) A[s] = __fmul_rn(A[s - 1], A[s - 1]);
    tree_scan(v, A, lane);                // membrane potential V

    // ===== Phase A (register-resident): gate mask + warp prefix =====
    // p > 0  <=>  cosf(2pi*U) > 0  (Eigen-sigmoid strictly positive).
    // cos>0 <=> |U - round(U)| < 0.25 up to rounding; margin fma(|U|,4e-7,.252)
    // over-covers all rounding paths. Over-inclusion safe (Phase B exact).
    unsigned gm = 0u;                     // lane-private gate mask over j=0..31
    #pragma unroll
    for (int j = 0; j < 32; j++) {
        float U = __fadd_rn(v[j], -1.0f);
        float w = __fadd_rn(U, -rintf(U));           // exact (Sterbenz)
        if (fabsf(w) < __fmaf_rn(fabsf(U), 4e-7f, 0.252f)) gm |= (1u << j);
    }
    int cnt  = __popc(gm);
    int incl = cnt;
    #pragma unroll
    for (int s = 1; s < 32; s <<= 1) {
        int tsh = __shfl_up_sync(FULLM, incl, s);
        if (lane >= s) incl += tsh;
    }
    int myoff = incl - cnt;                          // warp-exclusive prefix
    int total = __shfl_sync(FULLM, incl, 31);

    // ---- value-carrying emission: (V, t) pairs; v dies here; no writeback ----
    const int wtile = wrp << 10;
    #pragma unroll
    for (int j = 0; j < 32; j++) {
        if (gm & (1u << j)) {
            SB [wtile + myoff] = v[j];
            Lst[wtile + myoff] = (unsigned short)((lane << 5) + j);   // t
            myoff++;
        }
    }
    __syncwarp();   // own-warp STS -> cross-lane LDS

    // ===== Phase B: per-warp, 2-wide ILP, conflict-free sequential LDS =====
    const unsigned k2   = (unsigned)seedp[0];    // key=(0,seed): ks0=0
    const unsigned ks1  = k2;
    const unsigned ks2v = k2 ^ 0x1BD11BDAu;
    const unsigned CbaseC = (unsigned)(b * TT) * (unsigned)HH + (unsigned)(h0 + wrp);

    for (int s0 = 0; s0 < total; s0 += 64) {
        int r0 = s0 + lane;
        int r1 = s0 + 32 + lane;
        bool a0 = r0 < total, a1 = r1 < total;
        int rr0 = a0 ? r0 : total - 1;
        int rr1 = a1 ? r1 : total - 1;
        float V0 = SB[wtile + rr0];
        float V1 = SB[wtile + rr1];
        int   t0 = (int)Lst[wtile + rr0];
        int   t1 = (int)Lst[wtile + rr1];
        unsigned gi0 = CbaseC + (unsigned)t0 * (unsigned)HH;
        unsigned gi1 = CbaseC + (unsigned)t1 * (unsigned)HH;
        bool s0k = spike_eval(V0, gi0, ks1, ks2v);
        bool s1k = spike_eval(V1, gi1, ks1, ks2v);
        if (a0 && s0k) out[gi0] = 1.0f;   // overwrite the zero
        if (a1 && s1k) out[gi1] = 1.0f;   // (dup ranks write same value: benign)
    }
}

extern "C" void kernel_launch(void* const* d_in, const int* in_sizes, int n_in,
                              void* d_out, int out_size) {
    const float* u     = (const float*)d_in[0];
    const float* alpha = (const float*)d_in[1];
    const float* beta  = (const float*)d_in[2];
    const int*   seed  = (const int*)d_in[3];
    float* out = (float*)d_out;
    (void)in_sizes; (void)n_in; (void)out_size;

    dim3 grid(BB * (HH / HC));   // 4096 CTAs
    cubalif_kernel<<<grid, NTHR>>>(u, alpha, beta, seed, out);
}